// round 11
// baseline (speedup 1.0000x reference)
#include <cuda_runtime.h>
#include <cstdint>

// TropicalLinear forward on GB300:
//   out[n,o] = max_i( x[n,i] + w[o,i] ) + bias[o]
//
// R9: R8 + coalesced staging (the R8 killer was nL=32 scattered staging LDGs:
//     ~6144 L1tex wavefront-cycles/SM before compute).
//   - row-coalesced LDG -> transposing STS into padded k-major tiles:
//       ws  stride 130 (compute 2xLDS.64, conflict-free, aligned all k)
//       xs2 stride 132 (dup pairs, compute LDS.128 broadcast, aligned all k)
//   - acc o-mapping {2tx,2tx+1,64+2tx,64+2tx+1}: w LDS.64 IS the packed o-pair
//   - 256 CTAs, __launch_bounds__(512,2) -> 2 CTAs/SM, ticket barrier, fused
//     combine (16 partials + bias).

#define N_ROWS  128
#define IN_DIM  1024
#define OUT_DIM 1024
#define SPLIT   16
#define KC      (IN_DIM / SPLIT)   // 64 k per CTA
#define KS      64
#define TN      64
#define TO      128
#define NCTA    256
#define WSTR    130                // ws row stride (floats)
#define XSTR    132                // xs2 row stride (floats)

// 16 * 128 * 1024 floats = 8 MB static scratch (allocation-free rule)
__device__ float        g_part[SPLIT * N_ROWS * OUT_DIM];
__device__ unsigned int g_arrive;   // zero-init; monotonic across replays

__device__ __forceinline__ float neg_inf() { return __int_as_float(0xff800000); }

__device__ __forceinline__ unsigned long long add2(unsigned long long a,
                                                   unsigned long long b) {
    unsigned long long r;
    asm("add.rn.f32x2 %0, %1, %2;" : "=l"(r) : "l"(a), "l"(b));
    return r;
}
__device__ __forceinline__ float lo32(unsigned long long v) {
    return __uint_as_float((unsigned int)v);
}
__device__ __forceinline__ float hi32(unsigned long long v) {
    return __uint_as_float((unsigned int)(v >> 32));
}

extern "C" __global__ void __launch_bounds__(512, 2)
tropical_fused_kernel(const float* __restrict__ x,
                      const float* __restrict__ w,
                      const float* __restrict__ bias,
                      float* __restrict__ out)
{
    // xs2: [KS][XSTR] = 64*132*4 = 33792 B (x duplicated (v,v) pairs, k-major)
    // ws : [KS][WSTR] = 64*130*4 = 33280 B (w, k-major)
    extern __shared__ float smem[];
    float* xs2 = smem;                 // k-major, duplicated x
    float* ws  = smem + KS * XSTR;     // k-major w

    const int tid = threadIdx.x;
    const int tx  = tid & 31;          // o-direction lane
    const int ty  = tid >> 5;          // n-direction (16 warps x 4 rows)

    const int o0 = blockIdx.x * TO;
    const int n0 = blockIdx.y * TN;
    const int k0 = blockIdx.z * KC;
    const int flat_cta = blockIdx.x + blockIdx.y * 8 + blockIdx.z * 16; // 0..255

    // ---- stage tiles: row-coalesced LDG, transposing STS ----
    // w tile: 128 rows x 16 float4 (each row = 256B, 16 lanes) -> 4/thread
    {
        const int row = tid >> 4;          // 0..31  (+32 per iter)
        const int c4  = tid & 15;          // k-group
#pragma unroll
        for (int i = 0; i < 4; ++i) {
            const int r = row + i * 32;
            float4 v = *(const float4*)(w + (size_t)(o0 + r) * IN_DIM + k0 + c4 * 4);
            ws[(c4 * 4 + 0) * WSTR + r] = v.x;
            ws[(c4 * 4 + 1) * WSTR + r] = v.y;
            ws[(c4 * 4 + 2) * WSTR + r] = v.z;
            ws[(c4 * 4 + 3) * WSTR + r] = v.w;
        }
        // x tile: 64 rows x 16 float4 -> 2/thread, stored as dup pairs
#pragma unroll
        for (int i = 0; i < 2; ++i) {
            const int r = row + i * 32;
            float4 v = *(const float4*)(x + (size_t)(n0 + r) * IN_DIM + k0 + c4 * 4);
            *(float2*)&xs2[(c4 * 4 + 0) * XSTR + 2 * r] = make_float2(v.x, v.x);
            *(float2*)&xs2[(c4 * 4 + 1) * XSTR + 2 * r] = make_float2(v.y, v.y);
            *(float2*)&xs2[(c4 * 4 + 2) * XSTR + 2 * r] = make_float2(v.z, v.z);
            *(float2*)&xs2[(c4 * 4 + 3) * XSTR + 2 * r] = make_float2(v.w, v.w);
        }
    }
    __syncthreads();

    float acc[4][4];
#pragma unroll
    for (int i = 0; i < 4; ++i)
#pragma unroll
        for (int j = 0; j < 4; ++j)
            acc[i][j] = neg_inf();

    // ---- compute: per k = 2 bcast LDS.128 + 2 LDS.64 + 8 ADD2 + 16 FMNMX ----
    // xs2 reads: all lanes share ty -> warp broadcast.
    // ws reads: 16-lane phases hit banks 2k+2tx(+1) -> all 32 banks, clean.
#pragma unroll 8
    for (int k = 0; k < KS; ++k) {
        const ulonglong2 xa = *(const ulonglong2*)&xs2[k * XSTR + ty * 8];
        const ulonglong2 xb = *(const ulonglong2*)&xs2[k * XSTR + ty * 8 + 4];
        const unsigned long long wl = *(const unsigned long long*)&ws[k * WSTR + 2 * tx];
        const unsigned long long wh = *(const unsigned long long*)&ws[k * WSTR + 64 + 2 * tx];
        unsigned long long xd[4] = {xa.x, xa.y, xb.x, xb.y};
#pragma unroll
        for (int i = 0; i < 4; ++i) {
            unsigned long long s0 = add2(xd[i], wl);   // o = 2tx, 2tx+1
            unsigned long long s1 = add2(xd[i], wh);   // o = 64+2tx, 64+2tx+1
            acc[i][0] = fmaxf(acc[i][0], lo32(s0));
            acc[i][1] = fmaxf(acc[i][1], hi32(s0));
            acc[i][2] = fmaxf(acc[i][2], lo32(s1));
            acc[i][3] = fmaxf(acc[i][3], hi32(s1));
        }
    }

    // ---- write partial maxes (float2 per half, coalesced 256B/warp) ----
    float* pbase = g_part + (size_t)blockIdx.z * (N_ROWS * OUT_DIM);
#pragma unroll
    for (int i = 0; i < 4; ++i) {
        const int row = n0 + ty * 4 + i;
        *(float2*)(pbase + (size_t)row * OUT_DIM + o0 + 2 * tx)      = make_float2(acc[i][0], acc[i][1]);
        *(float2*)(pbase + (size_t)row * OUT_DIM + o0 + 64 + 2 * tx) = make_float2(acc[i][2], acc[i][3]);
    }

    // ---- grid-wide barrier: monotonic ticket epochs (replay-safe) ----
    __threadfence();
    __syncthreads();
    if (tid == 0) {
        unsigned int ticket = atomicAdd(&g_arrive, 1u) + 1u;
        unsigned int target = ((ticket + NCTA - 1u) / NCTA) * NCTA;
        unsigned int v;
        do {
            asm volatile("ld.acquire.gpu.u32 %0, [%1];"
                         : "=r"(v) : "l"(&g_arrive) : "memory");
        } while (v < target);
    }
    __syncthreads();

    // ---- fused combine: CTAs 0..127 each reduce one output row ----
    if (flat_cta < N_ROWS && tid < 256) {
        const int n  = flat_cta;
        const int o4 = tid * 4;
        const float* p = g_part + (size_t)n * OUT_DIM + o4;
        float4 m = make_float4(neg_inf(), neg_inf(), neg_inf(), neg_inf());
#pragma unroll
        for (int s = 0; s < SPLIT; ++s) {
            float4 v = __ldcg((const float4*)(p + (size_t)s * (N_ROWS * OUT_DIM)));
            m.x = fmaxf(m.x, v.x);
            m.y = fmaxf(m.y, v.y);
            m.z = fmaxf(m.z, v.z);
            m.w = fmaxf(m.w, v.w);
        }
        float4 b = *(const float4*)(bias + o4);
        m.x += b.x; m.y += b.y; m.z += b.z; m.w += b.w;
        *(float4*)(out + (size_t)n * OUT_DIM + o4) = m;
    }
}

extern "C" void kernel_launch(void* const* d_in, const int* in_sizes, int n_in,
                              void* d_out, int out_size)
{
    const float* x    = (const float*)d_in[0];   // [128, 1024]
    const float* w    = (const float*)d_in[1];   // [1024, 1024]
    const float* bias = (const float*)d_in[2];   // [1024]
    float* out = (float*)d_out;                  // [128, 1024]

    const int smem_bytes = (KS * XSTR + KS * WSTR) * sizeof(float);  // 67072 B
    static bool attr_set = false;
    if (!attr_set) {
        cudaFuncSetAttribute(tropical_fused_kernel,
                             cudaFuncAttributeMaxDynamicSharedMemorySize, smem_bytes);
        attr_set = true;
    }

    dim3 grid(OUT_DIM / TO, N_ROWS / TN, SPLIT);  // (8, 2, 16) = 256 CTAs
    tropical_fused_kernel<<<grid, 512, smem_bytes>>>(x, w, bias, out);
}